// round 4
// baseline (speedup 1.0000x reference)
#include <cuda_runtime.h>
#include <cuda_fp16.h>
#include <cuda_bf16.h>

#define IN_F 100000
#define OUT_F 100000
#define BSZ 64

#define T_BLOCKS 1563   // ceil(IN_F/64) transpose tiles

// device-global scratch (allocation-free rule)
__device__ __half g_xT[(size_t)IN_F * BSZ];   // x transposed, fp16: [IN_F][64]
__device__ int2   g_edge[1600000];            // {col*128 (byte offset), value bits}
__device__ int    g_row_ptr[OUT_F + 1];

// ---------------------------------------------------------------------------
// prep kernel:
//   blocks [0, T_BLOCKS)        : transpose x -> g_xT (fp32 -> fp16)
//   blocks [T_BLOCKS, ...)      : normalize indices -> packed edges + row_ptr
// ---------------------------------------------------------------------------
__global__ void prep_kernel(const float* __restrict__ x,
                            const void*  __restrict__ rows_p,
                            const void*  __restrict__ cols_p,
                            const float* __restrict__ values,
                            int nnz) {
    if (blockIdx.x < T_BLOCKS) {
        __shared__ float tile[64][65];
        const int c0 = blockIdx.x * 64;
        const int t  = threadIdx.x;
        const int f  = t & 15;    // float4 lane within a 64-float row
        const int g  = t >> 4;    // 0..15

#pragma unroll
        for (int p = 0; p < 4; p++) {
            int b = p * 16 + g;
            int c = c0 + 4 * f;
            if (c < IN_F) {
                float4 v = *(const float4*)&x[(size_t)b * IN_F + c];
                tile[4 * f + 0][b] = v.x;
                tile[4 * f + 1][b] = v.y;
                tile[4 * f + 2][b] = v.z;
                tile[4 * f + 3][b] = v.w;
            }
        }
        __syncthreads();
#pragma unroll
        for (int p = 0; p < 4; p++) {
            int cl = p * 16 + g;
            if (c0 + cl < IN_F) {
                __half2 h0 = __floats2half2_rn(tile[cl][4 * f + 0], tile[cl][4 * f + 1]);
                __half2 h1 = __floats2half2_rn(tile[cl][4 * f + 2], tile[cl][4 * f + 3]);
                uint2 pk;
                pk.x = *(unsigned*)&h0;
                pk.y = *(unsigned*)&h1;
                *(uint2*)&g_xT[(size_t)(c0 + cl) * BSZ + 4 * f] = pk;
            }
        }
    } else {
        // index-width detection: cols uniform in [0,1e5); int64 => odd words 0
        __shared__ int s_is64;
        if (threadIdx.x == 0) {
            const int* c32 = (const int*)cols_p;
            int fl = 1;
#pragma unroll
            for (int i = 0; i < 8; i++)
                if (c32[2 * i + 1] != 0) fl = 0;
            s_is64 = fl;
        }
        __syncthreads();

        int e = (blockIdx.x - T_BLOCKS) * 256 + threadIdx.x;
        if (e < nnz) {
            int c, r, pr;
            if (s_is64) {
                c  = (int)((const long long*)cols_p)[e];
                r  = (int)((const long long*)rows_p)[e];
                pr = (e > 0) ? (int)((const long long*)rows_p)[e - 1] : -1;
            } else {
                c  = ((const int*)cols_p)[e];
                r  = ((const int*)rows_p)[e];
                pr = (e > 0) ? ((const int*)rows_p)[e - 1] : -1;
            }
            g_edge[e] = make_int2(c << 7, __float_as_int(values[e]));

            // lower_bound semantics: row_ptr[o] = first edge with rows >= o
            for (int o = pr + 1; o <= r; o++) g_row_ptr[o] = e;
            if (e == nnz - 1)
                for (int o = r + 1; o <= OUT_F; o++) g_row_ptr[o] = nnz;
        }
    }
}

// ---------------------------------------------------------------------------
// fused SpMM: 32 warps/block, one output row per warp. Packed-edge stream
// (LDG.128 per 2 edges), fp16 128B-coalesced gather, fp32 register accum,
// smem transpose, coalesced direct write of out + bias.
// ---------------------------------------------------------------------------
__global__ __launch_bounds__(1024) void spmm_kernel(const float* __restrict__ bias,
                                                    float* __restrict__ out) {
    __shared__ float tile[64][33];   // [batch][o-within-block]
    const int w    = threadIdx.x >> 5;
    const int lane = threadIdx.x & 31;
    const int o    = blockIdx.x * 32 + w;   // OUT_F = 3125*32 exactly

    const int s = g_row_ptr[o];
    const int E = g_row_ptr[o + 1];

    const char* __restrict__ xbase = (const char*)g_xT + lane * 4;

    float2 a0 = make_float2(0.f, 0.f);
    float2 a1 = make_float2(0.f, 0.f);

    int e = s;
    // head-align to even edge index for int4 loads
    if (e < E && (e & 1)) {
        int2 ed = g_edge[e];
        float  v  = __int_as_float(ed.y);
        float2 xv = __half22float2(*(const __half2*)(xbase + ed.x));
        a0.x = fmaf(v, xv.x, a0.x); a0.y = fmaf(v, xv.y, a0.y);
        e++;
    }
#pragma unroll 2
    for (; e + 1 < E; e += 2) {
        int4 ed = *(const int4*)&g_edge[e];
        __half2 h0 = *(const __half2*)(xbase + ed.x);
        __half2 h1 = *(const __half2*)(xbase + ed.z);
        float v0 = __int_as_float(ed.y);
        float v1 = __int_as_float(ed.w);
        float2 x0 = __half22float2(h0);
        float2 x1 = __half22float2(h1);
        a0.x = fmaf(v0, x0.x, a0.x); a0.y = fmaf(v0, x0.y, a0.y);
        a1.x = fmaf(v1, x1.x, a1.x); a1.y = fmaf(v1, x1.y, a1.y);
    }
    if (e < E) {
        int2 ed = g_edge[e];
        float  v  = __int_as_float(ed.y);
        float2 xv = __half22float2(*(const __half2*)(xbase + ed.x));
        a0.x = fmaf(v, xv.x, a0.x); a0.y = fmaf(v, xv.y, a0.y);
    }

    tile[2 * lane + 0][w] = a0.x + a1.x;
    tile[2 * lane + 1][w] = a0.y + a1.y;
    __syncthreads();

    // write phase: thread t -> batch b = t/16, output pair oo = 2*(t%16)
    const int b  = threadIdx.x >> 4;
    const int j  = threadIdx.x & 15;
    const int oo = blockIdx.x * 32 + 2 * j;
    float2 bv = *(const float2*)&bias[oo];
    float2 r;
    r.x = tile[b][2 * j + 0] + bv.x;
    r.y = tile[b][2 * j + 1] + bv.y;
    *(float2*)&out[(size_t)b * OUT_F + oo] = r;
}

// ---------------------------------------------------------------------------
extern "C" void kernel_launch(void* const* d_in, const int* in_sizes, int n_in,
                              void* d_out, int out_size) {
    const float* x      = (const float*)d_in[0];
    const float* values = (const float*)d_in[1];
    const float* bias   = (const float*)d_in[2];
    const void*  rows   = d_in[3];
    const void*  cols   = d_in[4];
    float* out = (float*)d_out;

    const int nnz      = in_sizes[1];
    const int e_blocks = (nnz + 255) / 256;

    // 1) fused: x transpose (fp32->fp16) + edge packing + row_ptr scatter
    prep_kernel<<<T_BLOCKS + e_blocks, 256>>>(x, rows, cols, values, nnz);

    // 2) fused gather/accumulate + transpose + bias + final write
    spmm_kernel<<<OUT_F / 32, 1024>>>(bias, out);
}